// round 10
// baseline (speedup 1.0000x reference)
#include <cuda_runtime.h>

// ---------------- problem constants ----------------
#define Tt   4
#define Bb   16
#define Cc   384
#define Nn   256        // H*W
#define NHh  8
#define HDd  48
#define BCN  (Bb*Cc*Nn)     // 1572864
#define TBCN (Tt*BCN)       // 6291456
#define ATTN_ELEMS ((size_t)Tt*Bb*NHh*Nn*Nn)  // 33554432

// ---------------- scratch ----------------
__device__ float g_xs[TBCN];
__device__ float g_q [TBCN];
__device__ float g_k [TBCN];
__device__ float g_v [TBCN];
__device__ float g_kt[TBCN];
__device__ float g_vt[TBCN];
__device__ float g_av[TBCN];
__device__ unsigned char g_attn[ATTN_ELEMS];
__device__ float g_qsum;

// ---------------- shortcut LIF: xs = lif(x, 1.0); also zero qsum ----------
__global__ void k_lif_x(const float* __restrict__ x) {
    int i = blockIdx.x * 256 + threadIdx.x;
    if (i == 0) g_qsum = 0.0f;
    if (i >= BCN) return;
    float v = 0.0f;
#pragma unroll
    for (int t = 0; t < Tt; t++) {
        float xt = x[(size_t)t * BCN + i];
        v = v + (xt - v) * 0.5f;
        float u = v - 1.0f;
        g_xs[(size_t)t * BCN + i] = (u >= 0.0f) ? 1.0f : 0.0f;
        if (u >= 0.0f) v = 0.0f;
    }
}

// ---------------- fused channel GEMM + (bias/BN) + LIF over t --------------
// tile 64d x 128n, per-thread 8d x 4n, double-buffered (1 sync per slab)
__global__ void __launch_bounds__(256)
k_cgemm(int mode,
        const float* __restrict__ wq, const float* __restrict__ wk,
        const float* __restrict__ wv,
        const float* __restrict__ k_bn, const float* __restrict__ v_bn,
        const float* __restrict__ proj_w, const float* __restrict__ proj_b,
        const float* __restrict__ proj_bn,
        const float* __restrict__ x, float* __restrict__ out_ext)
{
    const int nb = blockIdx.x * 128;
    int db, sel;
    const float *W, *bn, *bias;
    const float *S, *S2;
    float *out;
    float vth;
    if (mode == 0) {
        sel = blockIdx.y / 6;
        db  = (blockIdx.y % 6) * 64;
        W   = (sel == 0) ? wq : (sel == 1) ? wk : wv;
        bn  = (sel == 1) ? k_bn : (sel == 2) ? v_bn : nullptr;
        bias = nullptr;
        vth = (sel == 0) ? 0.05f : 1.0f;
        out = (sel == 0) ? g_q : (sel == 1) ? g_k : g_v;
        S = g_xs; S2 = nullptr;
    } else {
        db = blockIdx.y * 64;
        W = proj_w; bn = proj_bn; bias = proj_b; vth = 1.0f;
        out = out_ext; S = g_av; S2 = x;
    }
    const int b = blockIdx.z;
    const int tid = threadIdx.x;
    const int tx = tid & 31, ty = tid >> 5;

    __shared__ __align__(16) float Ws[2][16][68];    // [buf][k][d]
    __shared__ __align__(16) float Ss[2][16][132];   // [buf][k][n]

    const int wdd = tid >> 2;
    const int wkk = (tid & 3) * 4;

    const size_t sbstride = (size_t)Cc * Nn;

    float vst[32];
#pragma unroll
    for (int i = 0; i < 32; i++) vst[i] = 0.0f;

    // ---- prologue: prefetch (t=0, c0=0), store to buf0, sync ----
    float4 wpre;
    float4 spre[2];
    {
        const float* Sb0  = S + (size_t)b * sbstride;
        const float* S2b0 = S2 ? (S2 + (size_t)b * sbstride) : nullptr;
        wpre = *(const float4*)&W[(size_t)(db + wdd) * Cc + wkk];
#pragma unroll
        for (int it = 0; it < 2; it++) {
            int r = it * 8 + ty;
            float4 sv = *(const float4*)&Sb0[(size_t)r * Nn + nb + tx * 4];
            if (S2b0) {
                float4 s2 = *(const float4*)&S2b0[(size_t)r * Nn + nb + tx * 4];
                sv.x += s2.x; sv.y += s2.y; sv.z += s2.z; sv.w += s2.w;
            }
            spre[it] = sv;
        }
    }
    Ws[0][wkk + 0][wdd] = wpre.x; Ws[0][wkk + 1][wdd] = wpre.y;
    Ws[0][wkk + 2][wdd] = wpre.z; Ws[0][wkk + 3][wdd] = wpre.w;
#pragma unroll
    for (int it = 0; it < 2; it++) {
        int r = it * 8 + ty;
        *(float4*)&Ss[0][r][tx * 4] = spre[it];
    }
    __syncthreads();
    int cur = 0;

    for (int t = 0; t < Tt; t++) {
        float acc[32];
#pragma unroll
        for (int i = 0; i < 32; i++) acc[i] = 0.0f;

        for (int c0 = 0; c0 < Cc; c0 += 16) {
            // prefetch NEXT slab into regs (overlaps compute below)
            int tn = t, c0n = c0 + 16;
            if (c0n >= Cc) { tn = t + 1; c0n = 0; }
            const bool havenext = (tn < Tt);
            if (havenext) {
                wpre = *(const float4*)&W[(size_t)(db + wdd) * Cc + c0n + wkk];
                const float* Sbn  = S + (size_t)(tn * Bb + b) * sbstride;
                const float* S2bn = S2 ? (S2 + (size_t)(tn * Bb + b) * sbstride) : nullptr;
#pragma unroll
                for (int it = 0; it < 2; it++) {
                    int r = it * 8 + ty;
                    float4 sv = *(const float4*)&Sbn[(size_t)(c0n + r) * Nn + nb + tx * 4];
                    if (S2bn) {
                        float4 s2 = *(const float4*)&S2bn[(size_t)(c0n + r) * Nn + nb + tx * 4];
                        sv.x += s2.x; sv.y += s2.y; sv.z += s2.z; sv.w += s2.w;
                    }
                    spre[it] = sv;
                }
            }

            // compute from buf[cur]
#pragma unroll
            for (int k = 0; k < 16; k++) {
                float4 s4 = *(const float4*)&Ss[cur][k][tx * 4];
                float4 wA = *(const float4*)&Ws[cur][k][ty * 8];
                float4 wB = *(const float4*)&Ws[cur][k][ty * 8 + 4];
                acc[0]  += wA.x * s4.x; acc[1]  += wA.x * s4.y; acc[2]  += wA.x * s4.z; acc[3]  += wA.x * s4.w;
                acc[4]  += wA.y * s4.x; acc[5]  += wA.y * s4.y; acc[6]  += wA.y * s4.z; acc[7]  += wA.y * s4.w;
                acc[8]  += wA.z * s4.x; acc[9]  += wA.z * s4.y; acc[10] += wA.z * s4.z; acc[11] += wA.z * s4.w;
                acc[12] += wA.w * s4.x; acc[13] += wA.w * s4.y; acc[14] += wA.w * s4.z; acc[15] += wA.w * s4.w;
                acc[16] += wB.x * s4.x; acc[17] += wB.x * s4.y; acc[18] += wB.x * s4.z; acc[19] += wB.x * s4.w;
                acc[20] += wB.y * s4.x; acc[21] += wB.y * s4.y; acc[22] += wB.y * s4.z; acc[23] += wB.y * s4.w;
                acc[24] += wB.z * s4.x; acc[25] += wB.z * s4.y; acc[26] += wB.z * s4.z; acc[27] += wB.z * s4.w;
                acc[28] += wB.w * s4.x; acc[29] += wB.w * s4.y; acc[30] += wB.w * s4.z; acc[31] += wB.w * s4.w;
            }

            // store prefetched slab into the other buffer, single sync
            if (havenext) {
                int nxt = cur ^ 1;
                Ws[nxt][wkk + 0][wdd] = wpre.x; Ws[nxt][wkk + 1][wdd] = wpre.y;
                Ws[nxt][wkk + 2][wdd] = wpre.z; Ws[nxt][wkk + 3][wdd] = wpre.w;
#pragma unroll
                for (int it = 0; it < 2; it++) {
                    int r = it * 8 + ty;
                    *(float4*)&Ss[nxt][r][tx * 4] = spre[it];
                }
                __syncthreads();
            }
            cur ^= 1;
        }

        // epilogue: bias -> BN -> LIF -> store
#pragma unroll
        for (int i = 0; i < 8; i++) {
            int d = db + ty * 8 + i;
            float bval = bias ? bias[d] : 0.0f;
            float inv = 1.0f, mu = 0.0f, beta = 0.0f;
            if (bn) {
                float g = bn[d], be = bn[Cc + d], m = bn[2 * Cc + d], var = bn[3 * Cc + d];
                inv = g * (1.0f / sqrtf(var + 1e-5f));
                mu = m; beta = be;
            }
            float4 res;
            float* rp = (float*)&res;
#pragma unroll
            for (int j = 0; j < 4; j++) {
                float val = acc[i * 4 + j] + bval;
                if (bn) val = inv * (val - mu) + beta;
                int idx = i * 4 + j;
                float v = vst[idx];
                v = v + (val - v) * 0.5f;
                float u = v - vth;
                float s = (u >= 0.0f) ? 1.0f : 0.0f;
                vst[idx] = (u >= 0.0f) ? 0.0f : v;
                rp[j] = s;
            }
            *(float4*)&out[((size_t)(t * Bb + b) * Cc + d) * Nn + nb + tx * 4] = res;
        }
    }
}

// ---------------- TIM conv step: double-buffered, 1 sync per slab ----------
__global__ void __launch_bounds__(256)
k_tim4(const float* __restrict__ w, const float* __restrict__ bias, int step)
{
    const float* xt = g_q + (size_t)(step - 1) * BCN;
    float* qslot    = g_q + (size_t)step * BCN;

    const int nb = blockIdx.x * 64;
    const int ob = blockIdx.y * 32;
    const int b  = blockIdx.z;
    const int tid = threadIdx.x;
    const int tx = tid & 15, ty = tid >> 4;

    __shared__ __align__(16) float ws[2][40][36];
    __shared__ __align__(16) float xsh[2][8][72];

    int wo[5], wr[5];
    size_t wbase[5];
#pragma unroll
    for (int it = 0; it < 5; it++) {
        int l = tid + it * 256;
        wo[it] = l / 40; wr[it] = l % 40;
        wbase[it] = (size_t)(ob + wo[it]) * (Cc * 5) + wr[it];
    }
    int xil[3], xcol[3], xvalid[3], xinb[3];
    size_t xbase[3];
#pragma unroll
    for (int it = 0; it < 3; it++) {
        int l = tid + it * 256;
        xvalid[it] = (l < 544);
        int il = l / 68, col = l % 68;
        if (!xvalid[it]) { il = 0; col = 0; }
        xil[it] = il; xcol[it] = col;
        int n = nb - 2 + col;
        xinb[it] = (n >= 0 && n < Nn);
        xbase[it] = ((size_t)b * Cc + il) * Nn + (xinb[it] ? n : 0);
    }

    float acc[8];
#pragma unroll
    for (int i = 0; i < 8; i++) acc[i] = 0.0f;

    // prologue: load slab 0, store to buf0, sync
    float wreg[5], xreg[3];
#pragma unroll
    for (int it = 0; it < 5; it++) wreg[it] = w[wbase[it]];
#pragma unroll
    for (int it = 0; it < 3; it++)
        xreg[it] = (xvalid[it] && xinb[it]) ? xt[xbase[it]] : 0.0f;
#pragma unroll
    for (int it = 0; it < 5; it++) ws[0][wr[it]][wo[it]] = wreg[it];
#pragma unroll
    for (int it = 0; it < 3; it++)
        if (xvalid[it]) xsh[0][xil[it]][xcol[it]] = xreg[it];
    __syncthreads();
    int cur = 0;

    for (int c0 = 0; c0 < Cc; c0 += 8) {
        const bool havenext = (c0 + 8 < Cc);
        // prefetch next slab into regs
        if (havenext) {
#pragma unroll
            for (int it = 0; it < 5; it++) wreg[it] = w[wbase[it] + (c0 + 8) * 5];
#pragma unroll
            for (int it = 0; it < 3; it++)
                xreg[it] = (xvalid[it] && xinb[it])
                         ? xt[xbase[it] + (size_t)(c0 + 8) * Nn] : 0.0f;
        }

        // compute from buf[cur]
#pragma unroll
        for (int il = 0; il < 8; il++) {
            float xr[8];
            *(float4*)&xr[0] = *(const float4*)&xsh[cur][il][tx * 4];
            *(float4*)&xr[4] = *(const float4*)&xsh[cur][il][tx * 4 + 4];
#pragma unroll
            for (int k = 0; k < 5; k++) {
                float2 w2 = *(const float2*)&ws[cur][il * 5 + k][ty * 2];
                acc[0] += w2.x * xr[k + 0]; acc[1] += w2.x * xr[k + 1];
                acc[2] += w2.x * xr[k + 2]; acc[3] += w2.x * xr[k + 3];
                acc[4] += w2.y * xr[k + 0]; acc[5] += w2.y * xr[k + 1];
                acc[6] += w2.y * xr[k + 2]; acc[7] += w2.y * xr[k + 3];
            }
        }

        // store next slab, single sync
        if (havenext) {
            int nxt = cur ^ 1;
#pragma unroll
            for (int it = 0; it < 5; it++) ws[nxt][wr[it]][wo[it]] = wreg[it];
#pragma unroll
            for (int it = 0; it < 3; it++)
                if (xvalid[it]) xsh[nxt][xil[it]][xcol[it]] = xreg[it];
            __syncthreads();
        }
        cur ^= 1;
    }
#pragma unroll
    for (int i = 0; i < 2; i++) {
        int o = ob + ty * 2 + i;
        float bv = bias[o];
        size_t qi = ((size_t)b * Cc + o) * Nn + nb + tx * 4;
        float4 qv = *(const float4*)&qslot[qi];
        float* qp = (float*)&qv;
        float4 res;
        float* rp = (float*)&res;
#pragma unroll
        for (int j = 0; j < 4; j++) {
            float cval = acc[i * 4 + j] + bv;
            float v = cval * 0.5f;
            float s = (v - 0.3f >= 0.0f) ? 1.0f : 0.0f;
            rp[j] = s * 0.6f + qp[j] * 0.4f;
        }
        *(float4*)&qslot[qi] = res;
    }
}

// ---------------- final TIM output LIF(0.5) over t; count spikes ----------
__global__ void k_lif_qfinal() {
    int i = blockIdx.x * 256 + threadIdx.x;
    float cnt = 0.0f;
    if (i < BCN) {
        float v = 0.0f;
#pragma unroll
        for (int t = 0; t < Tt; t++) {
            float xt = g_q[(size_t)t * BCN + i];
            v = v + (xt - v) * 0.5f;
            float u = v - 0.5f;
            float s = (u >= 0.0f) ? 1.0f : 0.0f;
            g_q[(size_t)t * BCN + i] = s;
            if (u >= 0.0f) v = 0.0f;
            cnt += s;
        }
    }
    __shared__ float red[256];
    red[threadIdx.x] = cnt;
    __syncthreads();
    for (int o = 128; o > 0; o >>= 1) {
        if (threadIdx.x < o) red[threadIdx.x] += red[threadIdx.x + o];
        __syncthreads();
    }
    if (threadIdx.x == 0) atomicAdd(&g_qsum, red[0]);
}

// ---------------- dst: k_t/v_t = bn_last( heads @ dst_w^T ) ---------------
__global__ void __launch_bounds__(128)
k_dst(const float* __restrict__ dw, const float* __restrict__ dbn)
{
    int m0     = blockIdx.x * 128;
    int batch  = blockIdx.y;
    int tensor = blockIdx.z;
    const float* src = tensor ? g_v : g_k;
    float* dst       = tensor ? g_vt : g_kt;
    int tb = batch / NHh, h = batch % NHh;
    int tid = threadIdx.x;

    __shared__ float ks[48][128];
    __shared__ float wsm[48][48];
    for (int l = tid; l < 48 * 128; l += 128) {
        int d = l >> 7, mm = l & 127;
        ks[d][mm] = src[((size_t)tb * Cc + h * HDd + d) * Nn + m0 + mm];
    }
    for (int l = tid; l < 48 * 48; l += 128) wsm[l / 48][l % 48] = dw[l];
    __syncthreads();

    for (int e = 0; e < 48; e++) {
        float sum = 0.0f;
#pragma unroll
        for (int d = 0; d < 48; d++) sum += wsm[e][d] * ks[d][tid];
        float g = dbn[e], be = dbn[48 + e], mu = dbn[96 + e], var = dbn[144 + e];
        float val = g * (1.0f / sqrtf(var + 1e-5f)) * (sum - mu) + be;
        dst[((size_t)batch * HDd + e) * Nn + m0 + tid] = val;
    }
}

// ---------------- attn = q @ k_t^T, * c1, LIF(0.5) -> bytes, dbuf ----------
__global__ void __launch_bounds__(256) k_attn2()
{
    const int m0 = blockIdx.x * 128;
    const int n0 = blockIdx.y * 64;
    const int bh = blockIdx.z;
    const int b = bh >> 3, h = bh & 7;
    const int tid = threadIdx.x;
    const int tx = tid & 31, ty = tid >> 5;

    float mean = g_qsum / 6291456.0f;
    float arg  = mean * 48.0f + 1e-6f;
    float c1   = fminf(1.0f / sqrtf(arg), 10.0f);

    __shared__ __align__(16) float Qs[2][16][68];
    __shared__ __align__(16) float Ks[2][16][132];

    const int qr = tid >> 4, qc = (tid & 15) * 4;

    float vst[32];
#pragma unroll
    for (int i = 0; i < 32; i++) vst[i] = 0.0f;

    // prologue: prefetch (t=0, e0=0), store buf0, sync
    float4 qpre;
    float4 kpre[2];
    {
        const float* Qb0 = g_q  + ((size_t)b * Cc + h * HDd) * Nn;
        const float* Kb0 = g_kt + (size_t)(b * NHh + h) * HDd * Nn;
        qpre = *(const float4*)&Qb0[(size_t)qr * Nn + n0 + qc];
#pragma unroll
        for (int it = 0; it < 2; it++) {
            int r = it * 8 + ty;
            kpre[it] = *(const float4*)&Kb0[(size_t)r * Nn + m0 + tx * 4];
        }
    }
    *(float4*)&Qs[0][qr][qc] = qpre;
#pragma unroll
    for (int it = 0; it < 2; it++) {
        int r = it * 8 + ty;
        *(float4*)&Ks[0][r][tx * 4] = kpre[it];
    }
    __syncthreads();
    int cur = 0;

    for (int t = 0; t < Tt; t++) {
        float acc[32];
#pragma unroll
        for (int i = 0; i < 32; i++) acc[i] = 0.0f;

        for (int e0 = 0; e0 < HDd; e0 += 16) {
            // prefetch next (t,e0)
            int tn = t, e0n = e0 + 16;
            if (e0n >= HDd) { tn = t + 1; e0n = 0; }
            const bool havenext = (tn < Tt);
            if (havenext) {
                const float* Qbn = g_q  + ((size_t)(tn * Bb + b) * Cc + h * HDd) * Nn;
                const float* Kbn = g_kt + (size_t)((tn * Bb + b) * NHh + h) * HDd * Nn;
                qpre = *(const float4*)&Qbn[(size_t)(e0n + qr) * Nn + n0 + qc];
#pragma unroll
                for (int it = 0; it < 2; it++) {
                    int r = it * 8 + ty;
                    kpre[it] = *(const float4*)&Kbn[(size_t)(e0n + r) * Nn + m0 + tx * 4];
                }
            }

            // compute from buf[cur]
#pragma unroll
            for (int e = 0; e < 16; e++) {
                float4 k4 = *(const float4*)&Ks[cur][e][tx * 4];
                float4 qA = *(const float4*)&Qs[cur][e][ty * 8];
                float4 qB = *(const float4*)&Qs[cur][e][ty * 8 + 4];
                acc[0]  += qA.x * k4.x; acc[1]  += qA.x * k4.y; acc[2]  += qA.x * k4.z; acc[3]  += qA.x * k4.w;
                acc[4]  += qA.y * k4.x; acc[5]  += qA.y * k4.y; acc[6]  += qA.y * k4.z; acc[7]  += qA.y * k4.w;
                acc[8]  += qA.z * k4.x; acc[9]  += qA.z * k4.y; acc[10] += qA.z * k4.z; acc[11] += qA.z * k4.w;
                acc[12] += qA.w * k4.x; acc[13] += qA.w * k4.y; acc[14] += qA.w * k4.z; acc[15] += qA.w * k4.w;
                acc[16] += qB.x * k4.x; acc[17] += qB.x * k4.y; acc[18] += qB.x * k4.z; acc[19] += qB.x * k4.w;
                acc[20] += qB.y * k4.x; acc[21] += qB.y * k4.y; acc[22] += qB.y * k4.z; acc[23] += qB.y * k4.w;
                acc[24] += qB.z * k4.x; acc[25] += qB.z * k4.y; acc[26] += qB.z * k4.z; acc[27] += qB.z * k4.w;
                acc[28] += qB.w * k4.x; acc[29] += qB.w * k4.y; acc[30] += qB.w * k4.z; acc[31] += qB.w * k4.w;
            }

            // store next slab, single sync
            if (havenext) {
                int nxt = cur ^ 1;
                *(float4*)&Qs[nxt][qr][qc] = qpre;
#pragma unroll
                for (int it = 0; it < 2; it++) {
                    int r = it * 8 + ty;
                    *(float4*)&Ks[nxt][r][tx * 4] = kpre[it];
                }
                __syncthreads();
            }
            cur ^= 1;
        }
#pragma unroll
        for (int i = 0; i < 8; i++) {
            int n = n0 + ty * 8 + i;
            uchar4 res;
            unsigned char* rp = (unsigned char*)&res;
#pragma unroll
            for (int j = 0; j < 4; j++) {
                float val = acc[i * 4 + j] * c1;
                int idx = i * 4 + j;
                float v = vst[idx];
                v = v + (val - v) * 0.5f;
                float u = v - 0.5f;
                vst[idx] = (u >= 0.0f) ? 0.0f : v;
                rp[j] = (u >= 0.0f) ? 1 : 0;
            }
            *(uchar4*)&g_attn[(((size_t)(t * Bb + b) * NHh + h) * Nn + n) * Nn + m0 + tx * 4] = res;
        }
    }
}

// ---------------- out_av = attn_map @ v_t (channel layout) ----------------
__global__ void __launch_bounds__(256) k_av()
{
    const int n0    = blockIdx.x * 128;
    const int batch = blockIdx.y;
    const int tb = batch / NHh, h = batch % NHh;
    const int tid = threadIdx.x;
    const int dg = tid >> 7;
    const int nl = tid & 127;

    __shared__ float vts[48][33];
    __shared__ float mps[128][33];

    float acc[24];
#pragma unroll
    for (int i = 0; i < 24; i++) acc[i] = 0.0f;

    for (int mc = 0; mc < 8; mc++) {
        int m0 = mc * 32;
        for (int l = tid; l < 48 * 32; l += 256) {
            int d = l >> 5, mm = l & 31;
            vts[d][mm] = g_vt[((size_t)batch * HDd + d) * Nn + m0 + mm];
        }
        for (int l = tid; l < 128 * 32; l += 256) {
            int nn = l >> 5, mm = l & 31;
            mps[nn][mm] = (float)g_attn[((size_t)batch * Nn + n0 + nn) * Nn + m0 + mm];
        }
        __syncthreads();
#pragma unroll
        for (int mm = 0; mm < 32; mm++) {
            float a = mps[nl][mm];
#pragma unroll
            for (int dd = 0; dd < 24; dd++)
                acc[dd] += vts[dg * 24 + dd][mm] * a;
        }
        __syncthreads();
    }
#pragma unroll
    for (int dd = 0; dd < 24; dd++) {
        int d = dg * 24 + dd;
        g_av[((size_t)tb * Cc + h * HDd + d) * Nn + n0 + nl] = acc[dd];
    }
}

// ---------------- v output copy into head layout --------------------------
__global__ void k_copy_v(float* __restrict__ dst) {
    int i = blockIdx.x * 256 + threadIdx.x;
    if (i >= TBCN) return;
    int d  = i % HDd;
    int n  = (i / HDd) % Nn;
    int h  = (i / (HDd * Nn)) % NHh;
    int tb = i / (HDd * Nn * NHh);
    dst[i] = g_v[((size_t)tb * Cc + h * HDd + d) * Nn + n];
}

// ---------------- launcher ----------------
extern "C" void kernel_launch(void* const* d_in, const int* in_sizes, int n_in,
                              void* d_out, int out_size)
{
    const float* x       = (const float*)d_in[0];
    const float* wq      = (const float*)d_in[1];
    const float* wk      = (const float*)d_in[2];
    const float* wv      = (const float*)d_in[3];
    const float* k_bn    = (const float*)d_in[4];
    const float* v_bn    = (const float*)d_in[5];
    const float* dst_w   = (const float*)d_in[6];
    const float* dst_bn  = (const float*)d_in[7];
    const float* proj_w  = (const float*)d_in[8];
    const float* proj_b  = (const float*)d_in[9];
    const float* proj_bn = (const float*)d_in[10];
    const float* tim_w   = (const float*)d_in[11];
    const float* tim_b   = (const float*)d_in[12];
    float* out = (float*)d_out;

    k_lif_x<<<BCN / 256, 256>>>(x);

    // fused q/k/v GEMM + LIF
    {
        dim3 g(Nn / 128, 18, Bb);   // (2,18,16)
        k_cgemm<<<g, 256>>>(0, wq, wk, wv, k_bn, v_bn,
                            nullptr, nullptr, nullptr, nullptr, nullptr);
    }
    // TIM: 3 sequential conv steps (in place in g_q)
    {
        dim3 g(Nn / 64, Cc / 32, Bb);  // (4,12,16) = 768 CTAs
        for (int step = 1; step < Tt; step++)
            k_tim4<<<g, 256>>>(tim_w, tim_b, step);
    }
    k_lif_qfinal<<<BCN / 256, 256>>>();

    {
        dim3 g(2, Tt * Bb * NHh, 2);
        k_dst<<<g, 128>>>(dst_w, dst_bn);
    }
    {
        dim3 g(Nn / 128, Nn / 64, Bb * NHh);  // (2,4,128)
        k_attn2<<<g, 256>>>();
    }
    {
        dim3 g(Nn / 128, Tt * Bb * NHh);
        k_av<<<g, 256>>>();
    }
    // proj GEMM + bias + BN + LIF -> d_out
    {
        dim3 g(Nn / 128, Cc / 64, Bb);
        k_cgemm<<<g, 256>>>(1, nullptr, nullptr, nullptr, nullptr, nullptr,
                            proj_w, proj_b, proj_bn, x, out);
    }
    if (out_size >= 2 * TBCN)
        k_copy_v<<<TBCN / 256, 256>>>(out + TBCN);
}

// round 11
// speedup vs baseline: 1.1500x; 1.1500x over previous
#include <cuda_runtime.h>

// ---------------- problem constants ----------------
#define Tt   4
#define Bb   16
#define Cc   384
#define Nn   256        // H*W
#define NHh  8
#define HDd  48
#define BCN  (Bb*Cc*Nn)     // 1572864
#define TBCN (Tt*BCN)       // 6291456
#define ATTN_ELEMS ((size_t)Tt*Bb*NHh*Nn*Nn)  // 33554432
#define MASKW 12            // 384 bits = 12 words

// ---------------- scratch ----------------
__device__ float g_q [TBCN];
__device__ float g_k [TBCN];
__device__ float g_v [TBCN];
__device__ float g_kt[TBCN];
__device__ float g_vt[TBCN];
__device__ float g_av[TBCN];
__device__ unsigned char g_attn[ATTN_ELEMS];
__device__ unsigned g_mask[(size_t)Tt*Bb*Nn*MASKW];  // xs spikes as bitmasks over c
__device__ float g_qsum;

// ---------------- shortcut LIF -> bitmasks (xs never materialized) --------
// grid (4 n-chunks, 16 b), 256 threads = 4 c_sub x 64 n
__global__ void __launch_bounds__(256) k_mask(const float* __restrict__ x) {
    const int nc = blockIdx.x, b = blockIdx.y;
    const int tid = threadIdx.x;
    const int nl   = tid & 63;
    const int csub = tid >> 6;
    const int n = nc * 64 + nl;

    __shared__ unsigned smask[Tt][64][MASKW];   // 12KB
    for (int l = tid; l < Tt * 64 * MASKW; l += 256)
        ((unsigned*)smask)[l] = 0u;
    if (tid == 0 && nc == 0 && b == 0) g_qsum = 0.0f;
    __syncthreads();

    for (int co = 0; co < 96; co++) {
        int c = co * 4 + csub;
        unsigned bit = 1u << (c & 31);
        int w = c >> 5;
        float v = 0.0f;
#pragma unroll
        for (int t = 0; t < Tt; t++) {
            float xt = x[((size_t)(t * Bb + b) * Cc + c) * Nn + n];
            v = v + (xt - v) * 0.5f;
            float u = v - 1.0f;
            if (u >= 0.0f) { atomicOr(&smask[t][nl][w], bit); v = 0.0f; }
        }
    }
    __syncthreads();
    for (int l = tid; l < Tt * 64 * MASKW; l += 256) {
        int t = l / (64 * MASKW);
        int r = l % (64 * MASKW);
        int nn = r / MASKW, w = r % MASKW;
        g_mask[((size_t)(t * Bb + b) * Nn + nc * 64 + nn) * MASKW + w] = smask[t][nn][w];
    }
}

// ---------------- sparse qkv: out = lif(BN(sum of active W columns)) ------
// grid (12 dblocks, 3 mats, 16 b), 256 threads.
// W tile [384c][32d] XOR-swizzled in 48KB static smem; ascending-c accumulation
// (bitwise identical to dense: skipped terms are exact +0.0f no-ops).
__global__ void __launch_bounds__(256)
k_sqkv(const float* __restrict__ wq, const float* __restrict__ wk,
       const float* __restrict__ wv,
       const float* __restrict__ k_bn, const float* __restrict__ v_bn)
{
    __shared__ float Wsm[384 * 32];   // 48KB exactly; addr = (c<<5) + (d ^ (c&31))

    const int dblk = blockIdx.x, mat = blockIdx.y, b = blockIdx.z;
    const float* W  = (mat == 0) ? wq : (mat == 1) ? wk : wv;
    const float* bn = (mat == 1) ? k_bn : (mat == 2) ? v_bn : nullptr;
    const float vth = (mat == 0) ? 0.05f : 1.0f;
    float* out      = (mat == 0) ? g_q : (mat == 1) ? g_k : g_v;
    const int db = dblk * 32;
    const int tid = threadIdx.x;
    const int lane = tid & 31;    // d within block
    const int wid  = tid >> 5;    // warp id 0..7

    // load W tile: 256 threads = 32 c-lanes x 8 d
    {
        const int clane = tid & 31;
        const int dsub  = tid >> 5;
#pragma unroll
        for (int dpass = 0; dpass < 4; dpass++) {
            int d = dpass * 8 + dsub;
#pragma unroll
            for (int cb = 0; cb < 384; cb += 32) {
                int c = cb + clane;
                Wsm[(c << 5) + (d ^ (c & 31))] = W[(size_t)(db + d) * Cc + c];
            }
        }
    }

    const int d = db + lane;
    float binv = 1.0f, bm = 0.0f, bb = 0.0f;
    if (bn) {
        float g = bn[d], be = bn[Cc + d], m = bn[2 * Cc + d], var = bn[3 * Cc + d];
        binv = g * (1.0f / sqrtf(var + 1e-5f));
        bm = m; bb = be;
    }
    __syncthreads();

    // each warp serves 4 n columns per 32-n chunk (serial; mask is uniform per warp)
    for (int nch = 0; nch < 8; nch++) {
        float res[4][4];   // [j][t]
#pragma unroll
        for (int j = 0; j < 4; j++) {
            int n = nch * 32 + wid * 4 + j;
            float vstt = 0.0f;
#pragma unroll
            for (int t = 0; t < Tt; t++) {
                const unsigned* m = &g_mask[((size_t)(t * Bb + b) * Nn + n) * MASKW];
                unsigned mw[MASKW];
#pragma unroll
                for (int w = 0; w < MASKW; w++) mw[w] = m[w];  // broadcast loads
                float sum = 0.0f;
#pragma unroll
                for (int w = 0; w < MASKW; w++) {
                    unsigned bits = mw[w];
                    while (bits) {
                        int c = (w << 5) + __ffs(bits) - 1;
                        bits &= bits - 1;
                        sum += Wsm[(c << 5) + (lane ^ (c & 31))];
                    }
                }
                float val = bn ? (binv * (sum - bm) + bb) : sum;
                float v2 = vstt + (val - vstt) * 0.5f;
                float u = v2 - vth;
                res[j][t] = (u >= 0.0f) ? 1.0f : 0.0f;
                vstt = (u >= 0.0f) ? 0.0f : v2;
            }
        }
#pragma unroll
        for (int t = 0; t < Tt; t++) {
            float4 r4 = make_float4(res[0][t], res[1][t], res[2][t], res[3][t]);
            *(float4*)&out[((size_t)(t * Bb + b) * Cc + d) * Nn + nch * 32 + wid * 4] = r4;
        }
    }
}

// ---------------- dense channel GEMM for proj (R8 version, mode1 only) ----
__global__ void __launch_bounds__(256)
k_cgemm(const float* __restrict__ proj_w, const float* __restrict__ proj_b,
        const float* __restrict__ proj_bn,
        const float* __restrict__ x, float* __restrict__ out_ext)
{
    const int nb = blockIdx.x * 128;
    const int db = blockIdx.y * 64;
    const float* W = proj_w; const float* bn = proj_bn; const float* bias = proj_b;
    const float vth = 1.0f;
    float* out = out_ext;
    const float* S = g_av; const float* S2 = x;
    const int b = blockIdx.z;
    const int tid = threadIdx.x;
    const int tx = tid & 31, ty = tid >> 5;

    __shared__ __align__(16) float Ws[16][64];
    __shared__ __align__(16) float Ss[16][128];

    const int wdd = tid >> 2;
    const int wkk = (tid & 3) * 4;

    float vst[32];
#pragma unroll
    for (int i = 0; i < 32; i++) vst[i] = 0.0f;

    for (int t = 0; t < Tt; t++) {
        float acc[32];
#pragma unroll
        for (int i = 0; i < 32; i++) acc[i] = 0.0f;

        const float* Sb  = S  + (size_t)(t * Bb + b) * Cc * Nn;
        const float* S2b = S2 + (size_t)(t * Bb + b) * Cc * Nn;

        for (int c0 = 0; c0 < Cc; c0 += 16) {
            float4 wv4 = *(const float4*)&W[(size_t)(db + wdd) * Cc + c0 + wkk];
            Ws[wkk + 0][wdd] = wv4.x; Ws[wkk + 1][wdd] = wv4.y;
            Ws[wkk + 2][wdd] = wv4.z; Ws[wkk + 3][wdd] = wv4.w;
#pragma unroll
            for (int it = 0; it < 2; it++) {
                int r = it * 8 + ty;
                float4 sv = *(const float4*)&Sb[(size_t)(c0 + r) * Nn + nb + tx * 4];
                float4 s2 = *(const float4*)&S2b[(size_t)(c0 + r) * Nn + nb + tx * 4];
                sv.x += s2.x; sv.y += s2.y; sv.z += s2.z; sv.w += s2.w;
                *(float4*)&Ss[r][tx * 4] = sv;
            }
            __syncthreads();
#pragma unroll
            for (int k = 0; k < 16; k++) {
                float4 s4 = *(const float4*)&Ss[k][tx * 4];
                float4 wA = *(const float4*)&Ws[k][ty * 8];
                float4 wB = *(const float4*)&Ws[k][ty * 8 + 4];
                acc[0]  += wA.x * s4.x; acc[1]  += wA.x * s4.y; acc[2]  += wA.x * s4.z; acc[3]  += wA.x * s4.w;
                acc[4]  += wA.y * s4.x; acc[5]  += wA.y * s4.y; acc[6]  += wA.y * s4.z; acc[7]  += wA.y * s4.w;
                acc[8]  += wA.z * s4.x; acc[9]  += wA.z * s4.y; acc[10] += wA.z * s4.z; acc[11] += wA.z * s4.w;
                acc[12] += wA.w * s4.x; acc[13] += wA.w * s4.y; acc[14] += wA.w * s4.z; acc[15] += wA.w * s4.w;
                acc[16] += wB.x * s4.x; acc[17] += wB.x * s4.y; acc[18] += wB.x * s4.z; acc[19] += wB.x * s4.w;
                acc[20] += wB.y * s4.x; acc[21] += wB.y * s4.y; acc[22] += wB.y * s4.z; acc[23] += wB.y * s4.w;
                acc[24] += wB.z * s4.x; acc[25] += wB.z * s4.y; acc[26] += wB.z * s4.z; acc[27] += wB.z * s4.w;
                acc[28] += wB.w * s4.x; acc[29] += wB.w * s4.y; acc[30] += wB.w * s4.z; acc[31] += wB.w * s4.w;
            }
            __syncthreads();
        }

#pragma unroll
        for (int i = 0; i < 8; i++) {
            int d = db + ty * 8 + i;
            float bval = bias[d];
            float g = bn[d], be = bn[Cc + d], m = bn[2 * Cc + d], var = bn[3 * Cc + d];
            float inv = g * (1.0f / sqrtf(var + 1e-5f));
            float4 res;
            float* rp = (float*)&res;
#pragma unroll
            for (int j = 0; j < 4; j++) {
                float val = inv * ((acc[i * 4 + j] + bval) - m) + be;
                int idx = i * 4 + j;
                float v = vst[idx];
                v = v + (val - v) * 0.5f;
                float u = v - vth;
                float s = (u >= 0.0f) ? 1.0f : 0.0f;
                vst[idx] = (u >= 0.0f) ? 0.0f : v;
                rp[j] = s;
            }
            *(float4*)&out[((size_t)(t * Bb + b) * Cc + d) * Nn + nb + tx * 4] = res;
        }
    }
}

// ---------------- TIM conv step: R8 version (prefetch, single buffer) ------
__global__ void __launch_bounds__(256)
k_tim4(const float* __restrict__ w, const float* __restrict__ bias, int step)
{
    const float* xt = g_q + (size_t)(step - 1) * BCN;
    float* qslot    = g_q + (size_t)step * BCN;

    const int nb = blockIdx.x * 64;
    const int ob = blockIdx.y * 32;
    const int b  = blockIdx.z;
    const int tid = threadIdx.x;
    const int tx = tid & 15, ty = tid >> 4;

    __shared__ __align__(16) float ws[40][36];
    __shared__ __align__(16) float xsh[8][72];

    int wo[5], wr[5];
    size_t wbase[5];
#pragma unroll
    for (int it = 0; it < 5; it++) {
        int l = tid + it * 256;
        wo[it] = l / 40; wr[it] = l % 40;
        wbase[it] = (size_t)(ob + wo[it]) * (Cc * 5) + wr[it];
    }
    int xil[3], xcol[3], xvalid[3], xinb[3];
    size_t xbase[3];
#pragma unroll
    for (int it = 0; it < 3; it++) {
        int l = tid + it * 256;
        xvalid[it] = (l < 544);
        int il = l / 68, col = l % 68;
        if (!xvalid[it]) { il = 0; col = 0; }
        xil[it] = il; xcol[it] = col;
        int n = nb - 2 + col;
        xinb[it] = (n >= 0 && n < Nn);
        xbase[it] = ((size_t)b * Cc + il) * Nn + (xinb[it] ? n : 0);
    }

    float acc[8];
#pragma unroll
    for (int i = 0; i < 8; i++) acc[i] = 0.0f;

    float wreg[5], xreg[3];
#pragma unroll
    for (int it = 0; it < 5; it++) wreg[it] = w[wbase[it]];
#pragma unroll
    for (int it = 0; it < 3; it++)
        xreg[it] = (xvalid[it] && xinb[it]) ? xt[xbase[it]] : 0.0f;

    for (int c0 = 0; c0 < Cc; c0 += 8) {
#pragma unroll
        for (int it = 0; it < 5; it++)
            ws[wr[it]][wo[it]] = wreg[it];
#pragma unroll
        for (int it = 0; it < 3; it++)
            if (xvalid[it]) xsh[xil[it]][xcol[it]] = xreg[it];
        __syncthreads();

        if (c0 + 8 < Cc) {
#pragma unroll
            for (int it = 0; it < 5; it++) wreg[it] = w[wbase[it] + (c0 + 8) * 5];
#pragma unroll
            for (int it = 0; it < 3; it++)
                xreg[it] = (xvalid[it] && xinb[it])
                         ? xt[xbase[it] + (size_t)(c0 + 8) * Nn] : 0.0f;
        }

#pragma unroll
        for (int il = 0; il < 8; il++) {
            float xr[8];
            *(float4*)&xr[0] = *(const float4*)&xsh[il][tx * 4];
            *(float4*)&xr[4] = *(const float4*)&xsh[il][tx * 4 + 4];
#pragma unroll
            for (int k = 0; k < 5; k++) {
                float2 w2 = *(const float2*)&ws[il * 5 + k][ty * 2];
                acc[0] += w2.x * xr[k + 0]; acc[1] += w2.x * xr[k + 1];
                acc[2] += w2.x * xr[k + 2]; acc[3] += w2.x * xr[k + 3];
                acc[4] += w2.y * xr[k + 0]; acc[5] += w2.y * xr[k + 1];
                acc[6] += w2.y * xr[k + 2]; acc[7] += w2.y * xr[k + 3];
            }
        }
        __syncthreads();
    }
#pragma unroll
    for (int i = 0; i < 2; i++) {
        int o = ob + ty * 2 + i;
        float bv = bias[o];
        size_t qi = ((size_t)b * Cc + o) * Nn + nb + tx * 4;
        float4 qv = *(const float4*)&qslot[qi];
        float* qp = (float*)&qv;
        float4 res;
        float* rp = (float*)&res;
#pragma unroll
        for (int j = 0; j < 4; j++) {
            float cval = acc[i * 4 + j] + bv;
            float v = cval * 0.5f;
            float s = (v - 0.3f >= 0.0f) ? 1.0f : 0.0f;
            rp[j] = s * 0.6f + qp[j] * 0.4f;
        }
        *(float4*)&qslot[qi] = res;
    }
}

// ---------------- final TIM output LIF(0.5) over t; count spikes ----------
__global__ void k_lif_qfinal() {
    int i = blockIdx.x * 256 + threadIdx.x;
    float cnt = 0.0f;
    if (i < BCN) {
        float v = 0.0f;
#pragma unroll
        for (int t = 0; t < Tt; t++) {
            float xt = g_q[(size_t)t * BCN + i];
            v = v + (xt - v) * 0.5f;
            float u = v - 0.5f;
            float s = (u >= 0.0f) ? 1.0f : 0.0f;
            g_q[(size_t)t * BCN + i] = s;
            if (u >= 0.0f) v = 0.0f;
            cnt += s;
        }
    }
    __shared__ float red[256];
    red[threadIdx.x] = cnt;
    __syncthreads();
    for (int o = 128; o > 0; o >>= 1) {
        if (threadIdx.x < o) red[threadIdx.x] += red[threadIdx.x + o];
        __syncthreads();
    }
    if (threadIdx.x == 0) atomicAdd(&g_qsum, red[0]);
}

// ---------------- dst: k_t/v_t = bn_last( heads @ dst_w^T ) ---------------
__global__ void __launch_bounds__(128)
k_dst(const float* __restrict__ dw, const float* __restrict__ dbn)
{
    int m0     = blockIdx.x * 128;
    int batch  = blockIdx.y;
    int tensor = blockIdx.z;
    const float* src = tensor ? g_v : g_k;
    float* dst       = tensor ? g_vt : g_kt;
    int tb = batch / NHh, h = batch % NHh;
    int tid = threadIdx.x;

    __shared__ float ks[48][128];
    __shared__ float wsm[48][48];
    for (int l = tid; l < 48 * 128; l += 128) {
        int d = l >> 7, mm = l & 127;
        ks[d][mm] = src[((size_t)tb * Cc + h * HDd + d) * Nn + m0 + mm];
    }
    for (int l = tid; l < 48 * 48; l += 128) wsm[l / 48][l % 48] = dw[l];
    __syncthreads();

    for (int e = 0; e < 48; e++) {
        float sum = 0.0f;
#pragma unroll
        for (int d = 0; d < 48; d++) sum += wsm[e][d] * ks[d][tid];
        float g = dbn[e], be = dbn[48 + e], mu = dbn[96 + e], var = dbn[144 + e];
        float val = g * (1.0f / sqrtf(var + 1e-5f)) * (sum - mu) + be;
        dst[((size_t)batch * HDd + e) * Nn + m0 + tid] = val;
    }
}

// ---------------- attn = q @ k_t^T, * c1, LIF(0.5) -> bytes (R8) ----------
__global__ void __launch_bounds__(256) k_attn2()
{
    const int m0 = blockIdx.x * 128;
    const int n0 = blockIdx.y * 64;
    const int bh = blockIdx.z;
    const int b = bh >> 3, h = bh & 7;
    const int tid = threadIdx.x;
    const int tx = tid & 31, ty = tid >> 5;

    float mean = g_qsum / 6291456.0f;
    float arg  = mean * 48.0f + 1e-6f;
    float c1   = fminf(1.0f / sqrtf(arg), 10.0f);

    __shared__ __align__(16) float Qs[16][64];
    __shared__ __align__(16) float Ks[16][128];

    float vst[32];
#pragma unroll
    for (int i = 0; i < 32; i++) vst[i] = 0.0f;

    for (int t = 0; t < Tt; t++) {
        float acc[32];
#pragma unroll
        for (int i = 0; i < 32; i++) acc[i] = 0.0f;

        const float* Qb = g_q  + ((size_t)(t * Bb + b) * Cc + h * HDd) * Nn;
        const float* Kb = g_kt + (size_t)((t * Bb + b) * NHh + h) * HDd * Nn;

        for (int e0 = 0; e0 < HDd; e0 += 16) {
            {
                int r = tid >> 4, c4 = (tid & 15) * 4;
                *(float4*)&Qs[r][c4] = *(const float4*)&Qb[(size_t)(e0 + r) * Nn + n0 + c4];
            }
#pragma unroll
            for (int it = 0; it < 2; it++) {
                int r = it * 8 + ty;
                *(float4*)&Ks[r][tx * 4] = *(const float4*)&Kb[(size_t)(e0 + r) * Nn + m0 + tx * 4];
            }
            __syncthreads();
#pragma unroll
            for (int e = 0; e < 16; e++) {
                float4 k4 = *(const float4*)&Ks[e][tx * 4];
                float4 qA = *(const float4*)&Qs[e][ty * 8];
                float4 qB = *(const float4*)&Qs[e][ty * 8 + 4];
                acc[0]  += qA.x * k4.x; acc[1]  += qA.x * k4.y; acc[2]  += qA.x * k4.z; acc[3]  += qA.x * k4.w;
                acc[4]  += qA.y * k4.x; acc[5]  += qA.y * k4.y; acc[6]  += qA.y * k4.z; acc[7]  += qA.y * k4.w;
                acc[8]  += qA.z * k4.x; acc[9]  += qA.z * k4.y; acc[10] += qA.z * k4.z; acc[11] += qA.z * k4.w;
                acc[12] += qA.w * k4.x; acc[13] += qA.w * k4.y; acc[14] += qA.w * k4.z; acc[15] += qA.w * k4.w;
                acc[16] += qB.x * k4.x; acc[17] += qB.x * k4.y; acc[18] += qB.x * k4.z; acc[19] += qB.x * k4.w;
                acc[20] += qB.y * k4.x; acc[21] += qB.y * k4.y; acc[22] += qB.y * k4.z; acc[23] += qB.y * k4.w;
                acc[24] += qB.z * k4.x; acc[25] += qB.z * k4.y; acc[26] += qB.z * k4.z; acc[27] += qB.z * k4.w;
                acc[28] += qB.w * k4.x; acc[29] += qB.w * k4.y; acc[30] += qB.w * k4.z; acc[31] += qB.w * k4.w;
            }
            __syncthreads();
        }
#pragma unroll
        for (int i = 0; i < 8; i++) {
            int n = n0 + ty * 8 + i;
            uchar4 res;
            unsigned char* rp = (unsigned char*)&res;
#pragma unroll
            for (int j = 0; j < 4; j++) {
                float val = acc[i * 4 + j] * c1;
                int idx = i * 4 + j;
                float v = vst[idx];
                v = v + (val - v) * 0.5f;
                float u = v - 0.5f;
                vst[idx] = (u >= 0.0f) ? 0.0f : v;
                rp[j] = (u >= 0.0f) ? 1 : 0;
            }
            *(uchar4*)&g_attn[(((size_t)(t * Bb + b) * NHh + h) * Nn + n) * Nn + m0 + tx * 4] = res;
        }
    }
}

// ---------------- out_av = attn_map @ v_t (channel layout) ----------------
__global__ void __launch_bounds__(256) k_av()
{
    const int n0    = blockIdx.x * 128;
    const int batch = blockIdx.y;
    const int tb = batch / NHh, h = batch % NHh;
    const int tid = threadIdx.x;
    const int dg = tid >> 7;
    const int nl = tid & 127;

    __shared__ float vts[48][33];
    __shared__ float mps[128][33];

    float acc[24];
#pragma unroll
    for (int i = 0; i < 24; i++) acc[i] = 0.0f;

    for (int mc = 0; mc < 8; mc++) {
        int m0 = mc * 32;
        for (int l = tid; l < 48 * 32; l += 256) {
            int d = l >> 5, mm = l & 31;
            vts[d][mm] = g_vt[((size_t)batch * HDd + d) * Nn + m0 + mm];
        }
        for (int l = tid; l < 128 * 32; l += 256) {
            int nn = l >> 5, mm = l & 31;
            mps[nn][mm] = (float)g_attn[((size_t)batch * Nn + n0 + nn) * Nn + m0 + mm];
        }
        __syncthreads();
#pragma unroll
        for (int mm = 0; mm < 32; mm++) {
            float a = mps[nl][mm];
#pragma unroll
            for (int dd = 0; dd < 24; dd++)
                acc[dd] += vts[dg * 24 + dd][mm] * a;
        }
        __syncthreads();
    }
#pragma unroll
    for (int dd = 0; dd < 24; dd++) {
        int d = dg * 24 + dd;
        g_av[((size_t)tb * Cc + h * HDd + d) * Nn + n0 + nl] = acc[dd];
    }
}

// ---------------- v output copy into head layout --------------------------
__global__ void k_copy_v(float* __restrict__ dst) {
    int i = blockIdx.x * 256 + threadIdx.x;
    if (i >= TBCN) return;
    int d  = i % HDd;
    int n  = (i / HDd) % Nn;
    int h  = (i / (HDd * Nn)) % NHh;
    int tb = i / (HDd * Nn * NHh);
    dst[i] = g_v[((size_t)tb * Cc + h * HDd + d) * Nn + n];
}

// ---------------- launcher ----------------
extern "C" void kernel_launch(void* const* d_in, const int* in_sizes, int n_in,
                              void* d_out, int out_size)
{
    const float* x       = (const float*)d_in[0];
    const float* wq      = (const float*)d_in[1];
    const float* wk      = (const float*)d_in[2];
    const float* wv      = (const float*)d_in[3];
    const float* k_bn    = (const float*)d_in[4];
    const float* v_bn    = (const float*)d_in[5];
    const float* dst_w   = (const float*)d_in[6];
    const float* dst_bn  = (const float*)d_in[7];
    const float* proj_w  = (const float*)d_in[8];
    const float* proj_b  = (const float*)d_in[9];
    const float* proj_bn = (const float*)d_in[10];
    const float* tim_w   = (const float*)d_in[11];
    const float* tim_b   = (const float*)d_in[12];
    float* out = (float*)d_out;

    // shortcut LIF -> bitmasks
    {
        dim3 g(4, Bb);
        k_mask<<<g, 256>>>(x);
    }
    // sparse q/k/v (bitwise-identical: skips only exact-zero terms)
    {
        dim3 g(12, 3, Bb);
        k_sqkv<<<g, 256>>>(wq, wk, wv, k_bn, v_bn);
    }
    // TIM: 3 sequential conv steps (in place in g_q)
    {
        dim3 g(Nn / 64, Cc / 32, Bb);
        for (int step = 1; step < Tt; step++)
            k_tim4<<<g, 256>>>(tim_w, tim_b, step);
    }
    k_lif_qfinal<<<BCN / 256, 256>>>();

    {
        dim3 g(2, Tt * Bb * NHh, 2);
        k_dst<<<g, 128>>>(dst_w, dst_bn);
    }
    {
        dim3 g(Nn / 128, Nn / 64, Bb * NHh);
        k_attn2<<<g, 256>>>();
    }
    {
        dim3 g(Nn / 128, Tt * Bb * NHh);
        k_av<<<g, 256>>>();
    }
    // proj GEMM + bias + BN + LIF -> d_out
    {
        dim3 g(Nn / 128, Cc / 64, Bb);
        k_cgemm<<<g, 256>>>(proj_w, proj_b, proj_bn, x, out);
    }
    if (out_size >= 2 * TBCN)
        k_copy_v<<<TBCN / 256, 256>>>(out + TBCN);
}